// round 17
// baseline (speedup 1.0000x reference)
#include <cuda_runtime.h>
#include <cuda_bf16.h>
#include <cfloat>

// Problem constants (S=4096 tokens, D=1024 dim, E=64 experts)
constexpr int S   = 4096;
constexpr int D   = 1024;
constexpr int E   = 64;
constexpr int CAP = 512;          // 2 * ceil(S / (E/4))
constexpr int KSLICES = 4;        // split-K factor (K-slice = 256)
constexpr int KS      = D / KSLICES;
constexpr int NGATE   = S / 8;    // gate blocks (8 tokens each)
constexpr int ROW     = E * CAP;  // 32768 floats per token per tensor
// out layout (float32): [0] = l_aux, [1 .. 1+S*E*CAP) = combine, then dispatch

// Fill partition (in float4 units). Total n4 = 2*S*ROW/4 = 67108864.
constexpr long long GEMM_F4_PER_BLK = 16384;   // 256 KB x 1024 blocks = 256 MB
constexpr long long GATE_F4_PER_BLK = 8192;    // 128 KB x 512 blocks  =  64 MB
constexpr long long GEMM_F4_TOTAL   = GEMM_F4_PER_BLK * 1024;   // 16777216
constexpr long long GATE_F4_TOTAL   = GATE_F4_PER_BLK * NGATE;  //  4194304
constexpr long long FILL_BASE       = GEMM_F4_TOTAL + GATE_F4_TOTAL;
constexpr int       ZF_BLOCKS       = 5632;    // 128 KB chunks (7.0 TB/s shape)
constexpr long long ZF_CHUNK4       = 8192;    // 5632*8192 = 46137344 (rest)

// ---------------- scratch (device globals; no allocation allowed) ----------
__device__ float g_part[2 * KSLICES * S * E];    // split-K partial logits (8MB)
__device__ int   g_expert[S];
__device__ float g_gate[S];
__device__ int   g_loc[S];
__device__ float g_me_part[NGATE * E];
__device__ float g_laux;

// packed fp32x2 FMA: d = a*b + d on both 32-bit halves (sm_103a FFMA2)
__device__ __forceinline__ void fma2(unsigned long long& d,
                                     unsigned long long a,
                                     unsigned long long b) {
    asm("fma.rn.f32x2 %0, %1, %2, %0;" : "+l"(d) : "l"(a), "l"(b));
}

// ---------------- split-K GEMM (f32x2) + embedded fill ---------------------
// grid (64 tok-tiles, 2 gemms, 4 K-slices) = 1024 blocks. Tile 64x64,
// K-chunks of 64. Inner product uses packed fma.rn.f32x2 -> half the FMA
// instructions (issue-bound floor ~16us instead of ~31us). Each block also
// zeroes a contiguous 256KB slice of d_out, stores drained under compute.
__global__ __launch_bounds__(256) void gemm_kernel(
    const float* __restrict__ A1, const float* __restrict__ A2,
    const float* __restrict__ W1, const float* __restrict__ W2,
    float4* __restrict__ out4)
{
    const float* A = blockIdx.y ? A2 : A1;
    const float* W = blockIdx.y ? W2 : W1;
    float* out = g_part + ((size_t)(blockIdx.y * KSLICES + blockIdx.z)) * S * E;
    const int tok0 = blockIdx.x * 64;
    const int kt0  = blockIdx.z * KS;

    const int blin = blockIdx.x + 64 * (blockIdx.y + 2 * blockIdx.z); // 0..1023
    float4* fill = out4 + (long long)blin * GEMM_F4_PER_BLK;
    const float4 z = make_float4(0.f, 0.f, 0.f, 0.f);

    __shared__ float As[64 * 64];
    __shared__ float Ws[64 * 64];

    const int tid = threadIdx.x;
    const int lr  = tid >> 4;   // loader row base (0..15)
    const int lc  = tid & 15;   // loader float4 column (0..15)
    const int tr  = tid & 15;   // compute: token quad
    const int ec  = tid >> 4;   // compute: expert quad

    unsigned long long acc2[4][4];   // packed (even-k, odd-k) partial sums
#pragma unroll
    for (int i = 0; i < 4; i++)
#pragma unroll
        for (int j = 0; j < 4; j++) acc2[i][j] = 0ULL;

    float4 pa[4], pw[4];
#pragma unroll
    for (int p = 0; p < 4; p++) {
        int row = lr + p * 16;
        pa[p] = *(const float4*)&A[(size_t)(tok0 + row) * D + kt0 + lc * 4];
        pw[p] = *(const float4*)&W[(size_t)row * D + kt0 + lc * 4];
    }

    int it = 0;
    for (int kt = kt0; kt < kt0 + KS; kt += 64, it++) {
#pragma unroll
        for (int p = 0; p < 4; p++) {
            int row = lr + p * 16;
            int sc  = (lc ^ ((row >> 2) & 7)) * 4;
            *(float4*)&As[row * 64 + sc] = pa[p];
            *(float4*)&Ws[row * 64 + sc] = pw[p];
        }
        __syncthreads();

        if (kt + 64 < kt0 + KS) {
#pragma unroll
            for (int p = 0; p < 4; p++) {
                int row = lr + p * 16;
                pa[p] = *(const float4*)&A[(size_t)(tok0 + row) * D + kt + 64 + lc * 4];
                pw[p] = *(const float4*)&W[(size_t)row * D + kt + 64 + lc * 4];
            }
        }

        // embedded fill: 16 posted stores per thread, drain under compute
        {
            float4* fb = fill + (long long)it * 4096;
#pragma unroll
            for (int k = 0; k < 16; k++) fb[k * 256 + tid] = z;
        }

#pragma unroll
        for (int kk = 0; kk < 16; kk++) {
            ulonglong2 av[4], wv[4];
#pragma unroll
            for (int i = 0; i < 4; i++) {
                int tok = tr * 4 + i;
                av[i] = *(const ulonglong2*)&As[tok * 64 + ((kk ^ (tr & 7)) * 4)];
                int e = ec * 4 + i;
                wv[i] = *(const ulonglong2*)&Ws[e * 64 + ((kk ^ (ec & 7)) * 4)];
            }
#pragma unroll
            for (int i = 0; i < 4; i++)
#pragma unroll
                for (int j = 0; j < 4; j++) {
                    fma2(acc2[i][j], av[i].x, wv[j].x);
                    fma2(acc2[i][j], av[i].y, wv[j].y);
                }
        }
        __syncthreads();
    }

#pragma unroll
    for (int i = 0; i < 4; i++) {
        float r[4];
#pragma unroll
        for (int j = 0; j < 4; j++) {
            float2 f = *(float2*)&acc2[i][j];
            r[j] = f.x + f.y;
        }
        *(float4*)&out[(size_t)(tok0 + tr * 4 + i) * E + ec * 4] =
            make_float4(r[0], r[1], r[2], r[3]);
    }
}

// ---------------- gating (R12-proven) + embedded fill ----------------------
__global__ __launch_bounds__(256) void gate_kernel(float4* __restrict__ out4) {
    __shared__ float sMe[8 * 64];
    const int b    = blockIdx.x;
    const int tid  = threadIdx.x;
    const int lane = tid & 31;
    const int w    = tid >> 5;
    const int t    = b * 8 + w;

    float l1a = 0.f, l1b = 0.f, l2a = 0.f, l2b = 0.f;
#pragma unroll
    for (int kz = 0; kz < KSLICES; kz++) {
        const float* p1 = g_part + (size_t)kz * S * E + (size_t)t * E;
        const float* p2 = g_part + (size_t)(KSLICES + kz) * S * E + (size_t)t * E;
        l1a += p1[lane];  l1b += p1[32 + lane];
        l2a += p2[lane];  l2b += p2[32 + lane];
    }
    if (lane == 0) l1a = -1e9f;      // expert 0 excluded from group gating

    // embedded fill: 32 posted stores per thread, drain under the gating math
    {
        float4* fb = out4 + GEMM_F4_TOTAL + (long long)b * GATE_F4_PER_BLK;
        const float4 z = make_float4(0.f, 0.f, 0.f, 0.f);
#pragma unroll
        for (int k = 0; k < 32; k++) fb[k * 256 + tid] = z;
    }

    // ---- stage 1: top-16 of group logits (softmax monotone -> skip it)
    bool sela = false, selb = false;
#pragma unroll 1
    for (int it = 0; it < 16; it++) {
        float va = sela ? -FLT_MAX : l1a;
        float vb = selb ? -FLT_MAX : l1b;
        float v; int idx;
        if (vb > va) { v = vb; idx = lane + 32; } else { v = va; idx = lane; }
#pragma unroll
        for (int off = 16; off > 0; off >>= 1) {
            float ov = __shfl_xor_sync(0xffffffffu, v, off);
            int   oi = __shfl_xor_sync(0xffffffffu, idx, off);
            if (ov > v || (ov == v && oi < idx)) { v = ov; idx = oi; }
        }
        if (idx == lane) sela = true;
        else if (idx == lane + 32) selb = true;
    }

    // ---- stage 2: masked softmax over the 16 selected experts
    float va = sela ? l2a : -FLT_MAX;
    float vb = selb ? l2b : -FLT_MAX;
    float m; int ei;
    if (vb > va) { m = vb; ei = lane + 32; } else { m = va; ei = lane; }
#pragma unroll
    for (int off = 16; off > 0; off >>= 1) {
        float ov = __shfl_xor_sync(0xffffffffu, m, off);
        int   oi = __shfl_xor_sync(0xffffffffu, ei, off);
        if (ov > m || (ov == m && oi < ei)) { m = ov; ei = oi; }
    }

    float ea = sela ? expf(l2a - m) : 0.0f;
    float eb = selb ? expf(l2b - m) : 0.0f;
    float ssum = ea + eb;
#pragma unroll
    for (int off = 16; off > 0; off >>= 1)
        ssum += __shfl_xor_sync(0xffffffffu, ssum, off);
    float inv = 1.0f / ssum;

    if (lane == 0) { g_expert[t] = ei; g_gate[t] = inv; }

    sMe[w * 64 + lane]      = sela ? ea * inv : 0.0f;
    sMe[w * 64 + 32 + lane] = selb ? eb * inv : 0.0f;
    __syncthreads();
    if (tid < 64) {
        float s = 0.0f;
#pragma unroll
        for (int ww = 0; ww < 8; ww++) s += sMe[ww * 64 + tid];
        g_me_part[b * 64 + tid] = s;
    }
}

// ---------------- locations via match.any ballots + l_aux (proven) ---------
__global__ __launch_bounds__(1024) void loc_kernel() {
    __shared__ int   sCnt[128][E];     // per-window per-expert counts (32 KB)
    __shared__ float sPart[16][E];     // me reduction staging (4 KB)
    __shared__ float sMe[E];

    const int tid  = threadIdx.x;
    const int lane = tid & 31;
    const int wp   = tid >> 5;         // warp id 0..31

    for (int i = tid; i < 128 * E; i += 1024) ((int*)sCnt)[i] = 0;
    __syncthreads();

    int   eReg[4];
    unsigned mReg[4];
#pragma unroll
    for (int k = 0; k < 4; k++) {
        int win = wp + k * 32;
        int e   = g_expert[win * 32 + lane];
        unsigned mask = __match_any_sync(0xffffffffu, e);
        eReg[k] = e; mReg[k] = mask;
        if ((mask & ((1u << lane) - 1)) == 0)     // leader lane of group
            sCnt[win][e] = __popc(mask);
    }

    {   // me partial reduction over NGATE=512 gate blocks
        int e = tid & 63, i = tid >> 6;
        float s = 0.0f;
        for (int b = i * 32; b < (i + 1) * 32; b++) s += g_me_part[b * 64 + e];
        sPart[i][e] = s;
    }
    __syncthreads();

    if (tid < 64) {                    // exclusive window-scan; ce = total
        int run = 0;
#pragma unroll 4
        for (int win = 0; win < 128; win++) {
            int c = sCnt[win][tid];
            sCnt[win][tid] = run;
            run += c;
        }
        float me = 0.0f;
#pragma unroll
        for (int i = 0; i < 16; i++) me += sPart[i][tid];
        sMe[tid] = me * (float)run;
    }
    __syncthreads();

#pragma unroll
    for (int k = 0; k < 4; k++) {
        int win  = wp + k * 32;
        int rank = sCnt[win][eReg[k]] + __popc(mReg[k] & ((1u << lane) - 1));
        g_loc[win * 32 + lane] = rank;
    }

    if (tid == 0) {
        float sum = 0.0f;
        for (int ee = 0; ee < E; ee++) sum += sMe[ee];
        g_laux = sum * (1.0f / 65536.0f);   // sum(me*ce)/(S*S)/num_2nd*E*E
    }
}

// ---------------- remainder zero fill (128KB chunks, 7.0 TB/s shape) -------
__global__ __launch_bounds__(256) void zero_fill_kernel(
    float4* __restrict__ p4,
    float* __restrict__ out, long long n4, long long out_elems)
{
    const float4 z = make_float4(0.f, 0.f, 0.f, 0.f);
    float4* base = p4 + FILL_BASE + (long long)blockIdx.x * ZF_CHUNK4;
#pragma unroll 4
    for (int j = threadIdx.x; j < (int)ZF_CHUNK4; j += 256)
        base[j] = z;
    if (blockIdx.x == 0) {            // scalar tail (out_size % 4 elements)
        for (long long j = n4 * 4 + threadIdx.x; j < out_elems; j += 256)
            out[j] = 0.0f;
    }
}

// ---------------- sparse scatter into combine/dispatch + l_aux -------------
__global__ void scatter_kernel(float* __restrict__ out) {
    int s = blockIdx.x * 256 + threadIdx.x;
    if (s == 0) out[0] = g_laux;
    if (s >= S) return;
    int loc = g_loc[s];
    if (loc >= CAP) return;            // dropped token: everything stays 0
    size_t off = ((size_t)s * E + g_expert[s]) * CAP + loc;
    out[1 + off] = g_gate[s];
    out[1 + (size_t)S * ROW + off] = 1.0f;
}

// ---------------- launch ----------------------------------------------------
extern "C" void kernel_launch(void* const* d_in, const int* in_sizes, int n_in,
                              void* d_out, int out_size) {
    const float* input1 = (const float*)d_in[0];
    const float* input2 = (const float*)d_in[1];
    const float* wg1    = (const float*)d_in[2];
    const float* wg2    = (const float*)d_in[3];
    float* out = (float*)d_out;
    // Fill covers float4s of the raw buffer out[0..n4*4) plus scalar tail;
    // the l_aux slot (out[0]) is inside fill block 0 and is rewritten by
    // scatter_kernel, which runs last.
    float4* out4 = (float4*)out;

    const long long n4 = (long long)out_size / 4;   // 67108864 (tail 1 elem)

    gemm_kernel<<<dim3(S / 64, 2, KSLICES), 256>>>(input1, input2, wg1, wg2, out4);
    gate_kernel<<<NGATE, 256>>>(out4);
    loc_kernel<<<1, 1024>>>();
    zero_fill_kernel<<<ZF_BLOCKS, 256>>>(out4, out, n4, (long long)out_size);
    scatter_kernel<<<(S + 255) / 256, 256>>>(out);
}